// round 13
// baseline (speedup 1.0000x reference)
#include <cuda_runtime.h>

// Shapes fixed by the problem's setup_inputs().
#define B_  8
#define H_  16
#define NT_ 512
#define NV_ 576

#define EPS_MIN 1e-8f
#define EPS_MAX 1.0f

#define NBLK (18 * 16 * 16)   // diag grid size = 4608

// Per-layer diagonal accumulators (atomic float adds).
// Zero-initialized at module load; the last block re-zeroes them after
// consuming, so every kernel_launch call starts from zeros.
__device__ float g_tdiag[2 * B_ * NT_];   // 8192 floats = 2048 float4
__device__ float g_vdiag[2 * B_ * NV_];   // 9216 floats = 2304 float4

// Completion ticket; atomicInc with modulus NBLK-1 wraps back to 0.
__device__ unsigned int g_ticket;

// One block (256 threads) = 32(i) x 32(j) tile for one (layer, b).
// Hot loop + epilogue identical to the proven 7.05 TB/s configuration.
// Fused finalize: ONE GPU-scope fence per CTA (thread 0, after
// __syncthreads; cumulativity covers the whole CTA's atomics), one ticket
// atomic; the last CTA runs the float4 -log reduction and stores out[0].
__global__ __launch_bounds__(256)
void diag_kernel(const float* __restrict__ at0, const float* __restrict__ av0,
                 const float* __restrict__ at1, const float* __restrict__ av1,
                 float* __restrict__ out) {
    __shared__ float shV[32][33];   // P_v sums, stride-33 -> conflict-free transpose
    __shared__ float shP[32][33];   // prod tile for column reduction
    __shared__ bool  is_last;

    const int t = threadIdx.x;
    const int p = t & 7;            // float4 slot within row
    const int q = t >> 3;           // row (i for attn_t, j for attn_v)

    const int z     = blockIdx.z;
    const int layer = z >> 3;
    const int b     = z & 7;
    const int i0    = blockIdx.y * 32;
    const int j0    = blockIdx.x * 32;

    const float* __restrict__ at = layer ? at1 : at0;
    const float* __restrict__ av = layer ? av1 : av0;

    // Base pointers at h = 0; head stride in float4 units.
    const size_t hstride4 = (size_t)NT_ * NV_ / 4;   // 73728
    const float4* __restrict__ pt = (const float4*)(
        at + (((size_t)b * H_) * NT_ + (i0 + q)) * NV_ + (j0 + 4 * p));
    const float4* __restrict__ pv = (const float4*)(
        av + (((size_t)b * H_) * NV_ + (j0 + q)) * NT_ + (i0 + 4 * p));

    float4 st = make_float4(0.f, 0.f, 0.f, 0.f);
    float4 sv = make_float4(0.f, 0.f, 0.f, 0.f);
#pragma unroll
    for (int h = 0; h < H_; ++h) {
        const float4 a = pt[h * hstride4];
        const float4 v = pv[h * hstride4];
        st.x += a.x; st.y += a.y; st.z += a.z; st.w += a.w;
        sv.x += v.x; sv.y += v.y; sv.z += v.z; sv.w += v.w;
    }

    // Stage P_v sums: shV[j - j0][i - i0]
    shV[q][4 * p + 0] = sv.x;
    shV[q][4 * p + 1] = sv.y;
    shV[q][4 * p + 2] = sv.z;
    shV[q][4 * p + 3] = sv.w;
    __syncthreads();

    // prod for (i = i0+q, j = j0+4p+c): needs shV[4p+c][q] (conflict-free:
    // bank addr ≡ 4p+c+q mod 32, bijective over each warp).
    const float pr0 = st.x * shV[4 * p + 0][q];
    const float pr1 = st.y * shV[4 * p + 1][q];
    const float pr2 = st.z * shV[4 * p + 2][q];
    const float pr3 = st.w * shV[4 * p + 3][q];

    // Row sum over j: reduce the 8 threads (p = 0..7) sharing row q.
    float rs = (pr0 + pr1) + (pr2 + pr3);
    rs += __shfl_xor_sync(0xffffffffu, rs, 1);
    rs += __shfl_xor_sync(0xffffffffu, rs, 2);
    rs += __shfl_xor_sync(0xffffffffu, rs, 4);
    if (p == 0)
        atomicAdd(&g_tdiag[layer * (B_ * NT_) + b * NT_ + i0 + q], rs);

    // Column sums: stage prod tile, then read transposed.
    shP[q][4 * p + 0] = pr0;
    shP[q][4 * p + 1] = pr1;
    shP[q][4 * p + 2] = pr2;
    shP[q][4 * p + 3] = pr3;
    __syncthreads();

    // Thread handles column j = j0+q, rows i = 4p+c (conflict-free reads).
    float cs = shP[4 * p + 0][q] + shP[4 * p + 1][q]
             + shP[4 * p + 2][q] + shP[4 * p + 3][q];
    cs += __shfl_xor_sync(0xffffffffu, cs, 1);
    cs += __shfl_xor_sync(0xffffffffu, cs, 2);
    cs += __shfl_xor_sync(0xffffffffu, cs, 4);
    if (p == 0)
        atomicAdd(&g_vdiag[layer * (B_ * NV_) + b * NV_ + j0 + q], cs);

    // ---- fused finalize: single fence + ticket per CTA ----
    // All 16 atomicAdds above happen-before this barrier (bar.sync is CTA-
    // scope synchronizing); thread 0's cumulative GPU-scope fence then
    // orders them before its ticket increment. ONE MEMBAR per CTA (R4's
    // regression used 8).
    __syncthreads();
    if (t == 0) {
        __threadfence();
        unsigned int ticket = atomicInc(&g_ticket, NBLK - 1);
        is_last = (ticket == NBLK - 1);
    }
    __syncthreads();
    if (!is_last) return;

    // Consumer: acquire everything the other 4607 CTAs released.
    __threadfence();

    const float inv_h2  = 1.0f / (float)(H_ * H_);
    const float scale_t = 0.25f / (float)(B_ * NT_);
    const float scale_v = 0.25f / (float)(B_ * NV_);
    const float4 zero4  = make_float4(0.f, 0.f, 0.f, 0.f);

    float acc = 0.0f;
    float4* t4 = (float4*)g_tdiag;   // 2048 float4
    for (int i = t; i < 2048; i += 256) {
        float4 d = __ldcg(&t4[i]);
        __stcg(&t4[i], zero4);       // reset for next replay
        float v;
        v = fminf(fmaxf(d.x * inv_h2, EPS_MIN), EPS_MAX); acc -= __logf(v) * scale_t;
        v = fminf(fmaxf(d.y * inv_h2, EPS_MIN), EPS_MAX); acc -= __logf(v) * scale_t;
        v = fminf(fmaxf(d.z * inv_h2, EPS_MIN), EPS_MAX); acc -= __logf(v) * scale_t;
        v = fminf(fmaxf(d.w * inv_h2, EPS_MIN), EPS_MAX); acc -= __logf(v) * scale_t;
    }
    float4* v4 = (float4*)g_vdiag;   // 2304 float4
    for (int i = t; i < 2304; i += 256) {
        float4 d = __ldcg(&v4[i]);
        __stcg(&v4[i], zero4);
        float v;
        v = fminf(fmaxf(d.x * inv_h2, EPS_MIN), EPS_MAX); acc -= __logf(v) * scale_v;
        v = fminf(fmaxf(d.y * inv_h2, EPS_MIN), EPS_MAX); acc -= __logf(v) * scale_v;
        v = fminf(fmaxf(d.z * inv_h2, EPS_MIN), EPS_MAX); acc -= __logf(v) * scale_v;
        v = fminf(fmaxf(d.w * inv_h2, EPS_MIN), EPS_MAX); acc -= __logf(v) * scale_v;
    }

    // Intra-block reduction; reuse shV storage.
#pragma unroll
    for (int o = 16; o > 0; o >>= 1)
        acc += __shfl_xor_sync(0xffffffffu, acc, o);
    float* red = &shV[0][0];
    const int w = t >> 5, l = t & 31;
    if (l == 0) red[w] = acc;
    __syncthreads();
    if (t == 0) {
        float s = 0.0f;
#pragma unroll
        for (int k = 0; k < 8; ++k) s += red[k];
        out[0] = s;                  // direct store; no pre-zero needed
        // g_ticket already wrapped to 0 by atomicInc's modulus.
    }
}

extern "C" void kernel_launch(void* const* d_in, const int* in_sizes, int n_in,
                              void* d_out, int out_size) {
    const float* at0 = (const float*)d_in[0];
    const float* av0 = (const float*)d_in[1];
    const float* at1 = (const float*)d_in[2];
    const float* av1 = (const float*)d_in[3];

    // Single fused kernel: head-mean + diagonal row/col sums + last-block
    // scalar finalize (one fence + one ticket atomic per CTA).
    // grid: x = NV/32 = 18 j-tiles, y = NT/32 = 16 i-tiles, z = layer*8 + b
    dim3 grid(NV_ / 32, NT_ / 32, 2 * B_);
    diag_kernel<<<grid, 256>>>(at0, av0, at1, av1, (float*)d_out);
}

// round 14
// speedup vs baseline: 1.1155x; 1.1155x over previous
#include <cuda_runtime.h>

// Shapes fixed by the problem's setup_inputs().
#define B_  8
#define H_  16
#define NT_ 512
#define NV_ 576

#define EPS_MIN 1e-8f
#define EPS_MAX 1.0f

// Per-layer diagonal accumulators (atomic float adds).
// Zero-initialized at module load; finalize_kernel re-zeroes each element
// right after consuming it, so every kernel_launch call starts from zeros.
__device__ float g_tdiag[2 * B_ * NT_];   // 8192 floats = 2048 float4
__device__ float g_vdiag[2 * B_ * NV_];   // 9216 floats = 2304 float4

// One block (256 threads) = 32(i) x 32(j) tile for one (layer, b).
//   thread t: p = t & 7 (float4 slot), q = t >> 3 (row index 0..31)
//   attn_t: element (i = i0+q, j = j0+4p..+3)  -> float4 along j (contiguous)
//   attn_v: element (j = j0+q, i = i0+4p..+3)  -> float4 along i (contiguous)
// prod[i][j] = P_t_sum[i][j] * P_v_sum[j][i]; row sums -> g_tdiag,
// column sums -> g_vdiag.
// PROVEN configuration: 7.05 TB/s = 88% of HBM spec. Falsified alternatives:
// __ldcs (-13%), fused tail w/ 8 fences (-15%), fused tail w/ 1 fence (-15%),
// PDL (-2%), 64-wide tile (-5%), launch_bounds(256,8) (-2%), single-barrier
// epilogue (-3%). Do not perturb the hot loop, its registers, or its
// retirement path.
__global__ __launch_bounds__(256)
void diag_kernel(const float* __restrict__ at0, const float* __restrict__ av0,
                 const float* __restrict__ at1, const float* __restrict__ av1) {
    __shared__ float shV[32][33];   // P_v sums, stride-33 -> conflict-free transpose
    __shared__ float shP[32][33];   // prod tile for column reduction

    const int t = threadIdx.x;
    const int p = t & 7;            // float4 slot within row
    const int q = t >> 3;           // row (i for attn_t, j for attn_v)

    const int z     = blockIdx.z;
    const int layer = z >> 3;
    const int b     = z & 7;
    const int i0    = blockIdx.y * 32;
    const int j0    = blockIdx.x * 32;

    const float* __restrict__ at = layer ? at1 : at0;
    const float* __restrict__ av = layer ? av1 : av0;

    // Base pointers at h = 0; head stride in float4 units.
    const size_t hstride4 = (size_t)NT_ * NV_ / 4;   // 73728
    const float4* __restrict__ pt = (const float4*)(
        at + (((size_t)b * H_) * NT_ + (i0 + q)) * NV_ + (j0 + 4 * p));
    const float4* __restrict__ pv = (const float4*)(
        av + (((size_t)b * H_) * NV_ + (j0 + q)) * NT_ + (i0 + 4 * p));

    float4 st = make_float4(0.f, 0.f, 0.f, 0.f);
    float4 sv = make_float4(0.f, 0.f, 0.f, 0.f);
#pragma unroll
    for (int h = 0; h < H_; ++h) {
        const float4 a = pt[h * hstride4];
        const float4 v = pv[h * hstride4];
        st.x += a.x; st.y += a.y; st.z += a.z; st.w += a.w;
        sv.x += v.x; sv.y += v.y; sv.z += v.z; sv.w += v.w;
    }

    // Stage P_v sums: shV[j - j0][i - i0]
    shV[q][4 * p + 0] = sv.x;
    shV[q][4 * p + 1] = sv.y;
    shV[q][4 * p + 2] = sv.z;
    shV[q][4 * p + 3] = sv.w;
    __syncthreads();

    // prod for (i = i0+q, j = j0+4p+c): needs shV[4p+c][q] (conflict-free:
    // bank addr ≡ 4p+c+q mod 32, bijective over each warp).
    const float pr0 = st.x * shV[4 * p + 0][q];
    const float pr1 = st.y * shV[4 * p + 1][q];
    const float pr2 = st.z * shV[4 * p + 2][q];
    const float pr3 = st.w * shV[4 * p + 3][q];

    // Row sum over j: reduce the 8 threads (p = 0..7) sharing row q.
    float rs = (pr0 + pr1) + (pr2 + pr3);
    rs += __shfl_xor_sync(0xffffffffu, rs, 1);
    rs += __shfl_xor_sync(0xffffffffu, rs, 2);
    rs += __shfl_xor_sync(0xffffffffu, rs, 4);
    if (p == 0)
        atomicAdd(&g_tdiag[layer * (B_ * NT_) + b * NT_ + i0 + q], rs);

    // Column sums: stage prod tile, then read transposed.
    shP[q][4 * p + 0] = pr0;
    shP[q][4 * p + 1] = pr1;
    shP[q][4 * p + 2] = pr2;
    shP[q][4 * p + 3] = pr3;
    __syncthreads();

    // Thread handles column j = j0+q, rows i = 4p+c (conflict-free reads).
    float cs = shP[4 * p + 0][q] + shP[4 * p + 1][q]
             + shP[4 * p + 2][q] + shP[4 * p + 3][q];
    cs += __shfl_xor_sync(0xffffffffu, cs, 1);
    cs += __shfl_xor_sync(0xffffffffu, cs, 2);
    cs += __shfl_xor_sync(0xffffffffu, cs, 4);
    if (p == 0)
        atomicAdd(&g_vdiag[layer * (B_ * NV_) + b * NV_ + j0 + q], cs);
}

// Finalize: ONE block, 1024 threads, direct store to out[0].
// 2048 tdiag float4 + 2304 vdiag float4, ~4.25 vector loads per thread at
// L2 latency (the values were just written by atomics -> L2-resident).
// No atomics on out, no init needed in diag, no inter-block coordination.
// The kernel boundary orders all diag atomics before us.
__global__ __launch_bounds__(1024)
void finalize_kernel(float* __restrict__ out) {
    __shared__ float red[32];
    const int t = threadIdx.x;
    const float inv_h2  = 1.0f / (float)(H_ * H_);  // sums -> products of means
    const float scale_t = 0.25f / (float)(B_ * NT_);
    const float scale_v = 0.25f / (float)(B_ * NV_);
    const float4 zero4  = make_float4(0.f, 0.f, 0.f, 0.f);

    float acc = 0.0f;
    float4* t4 = (float4*)g_tdiag;   // 2048 float4
#pragma unroll
    for (int i = t; i < 2048; i += 1024) {
        float4 d = __ldcg(&t4[i]);
        __stcg(&t4[i], zero4);       // reset for next replay
        float v;
        v = fminf(fmaxf(d.x * inv_h2, EPS_MIN), EPS_MAX); acc -= __logf(v) * scale_t;
        v = fminf(fmaxf(d.y * inv_h2, EPS_MIN), EPS_MAX); acc -= __logf(v) * scale_t;
        v = fminf(fmaxf(d.z * inv_h2, EPS_MIN), EPS_MAX); acc -= __logf(v) * scale_t;
        v = fminf(fmaxf(d.w * inv_h2, EPS_MIN), EPS_MAX); acc -= __logf(v) * scale_t;
    }
    float4* v4 = (float4*)g_vdiag;   // 2304 float4
#pragma unroll
    for (int i = t; i < 2304; i += 1024) {
        float4 d = __ldcg(&v4[i]);
        __stcg(&v4[i], zero4);
        float v;
        v = fminf(fmaxf(d.x * inv_h2, EPS_MIN), EPS_MAX); acc -= __logf(v) * scale_v;
        v = fminf(fmaxf(d.y * inv_h2, EPS_MIN), EPS_MAX); acc -= __logf(v) * scale_v;
        v = fminf(fmaxf(d.z * inv_h2, EPS_MIN), EPS_MAX); acc -= __logf(v) * scale_v;
        v = fminf(fmaxf(d.w * inv_h2, EPS_MIN), EPS_MAX); acc -= __logf(v) * scale_v;
    }

#pragma unroll
    for (int o = 16; o > 0; o >>= 1)
        acc += __shfl_xor_sync(0xffffffffu, acc, o);
    const int w = t >> 5, l = t & 31;
    if (l == 0) red[w] = acc;
    __syncthreads();
    if (w == 0) {
        float s = red[l];
#pragma unroll
        for (int o = 16; o > 0; o >>= 1)
            s += __shfl_xor_sync(0xffffffffu, s, o);
        if (l == 0) out[0] = s;      // direct store; overwrites the poison
    }
}

extern "C" void kernel_launch(void* const* d_in, const int* in_sizes, int n_in,
                              void* d_out, int out_size) {
    const float* at0 = (const float*)d_in[0];
    const float* av0 = (const float*)d_in[1];
    const float* at1 = (const float*)d_in[2];
    const float* av1 = (const float*)d_in[3];

    // Fused head-mean + diagonal row/col sums.
    // grid: x = NV/32 = 18 j-tiles, y = NT/32 = 16 i-tiles, z = layer*8 + b
    dim3 grid(NV_ / 32, NT_ / 32, 2 * B_);
    diag_kernel<<<grid, 256>>>(at0, av0, at1, av1);

    // Single-block finalize: -log/clip reduction, direct store to out[0].
    finalize_kernel<<<1, 1024>>>((float*)d_out);
}